// round 2
// baseline (speedup 1.0000x reference)
#include <cuda_runtime.h>

#define P_PILLARS 96000
#define M_PTS 32
#define COUTC 64
#define NXC 432
#define NYC 496
#define NBC 8
#define NYNX (NXC * NYC)        /* 214272 */
#define Q4 (NYNX / 4)           /* 53568 */
#define PPB 8                   /* pillars per block in main kernel */

// ---------------- device scratch (no allocations allowed) ----------------
__device__ int   g_winner[NBC * NYNX];                    // 6.9 MB
__device__ float g_sumh[COUTC];
__device__ float g_sumh2[COUTC];
__device__ float g_a[COUTC];
__device__ float g_bb[COUTC];
__device__ float g_ext[(size_t)P_PILLARS * COUTC];        // 24.6 MB

// ---------------- init: winner = -1, stats = 0 ----------------
__global__ void pfe_init() {
    int i = blockIdx.x * blockDim.x + threadIdx.x;
    if (i < NBC * NYNX) g_winner[i] = -1;
    if (i < COUTC) { g_sumh[i] = 0.f; g_sumh2[i] = 0.f; }
}

// ---------------- main: per-pillar GEMM + stats + extremes + winner ------
__global__ __launch_bounds__(512) void pfe_main(
    const float* __restrict__ pillars,
    const int*   __restrict__ coords,
    const int*   __restrict__ num_points,
    const float* __restrict__ W,
    const float* __restrict__ gamma)
{
    __shared__ float4 sPts[PPB * M_PTS];   // 4 KB
    __shared__ float  sW[640];             // 2.5 KB
    __shared__ float4 sSum[PPB];
    __shared__ float  sRed[2 * PPB * COUTC];

    int t  = threadIdx.x;
    int lp = t >> 6;        // local pillar 0..7
    int c  = t & 63;        // channel
    int p  = blockIdx.x * PPB + lp;

    // cooperative coalesced loads
    const float4* gp = reinterpret_cast<const float4*>(pillars)
                       + (size_t)blockIdx.x * PPB * M_PTS;
    if (t < PPB * M_PTS) sPts[t] = gp[t];
    for (int i = t; i < 640; i += 512) sW[i] = W[i];
    __syncthreads();

    // per-pillar point sums (even warps, lane = point index)
    int warpId = t >> 5, lane = t & 31;
    if (!(warpId & 1)) {
        int lpp = warpId >> 1;
        float4 s = sPts[lpp * M_PTS + lane];
        #pragma unroll
        for (int o = 16; o; o >>= 1) {
            s.x += __shfl_down_sync(0xffffffffu, s.x, o);
            s.y += __shfl_down_sync(0xffffffffu, s.y, o);
            s.z += __shfl_down_sync(0xffffffffu, s.z, o);
            s.w += __shfl_down_sync(0xffffffffu, s.w, o);
        }
        if (lane == 0) sSum[lpp] = s;
    }
    __syncthreads();

    float4 S = sSum[lp];
    float n  = (float)num_points[p];
    float mx = S.x / n, my = S.y / n, mz = S.z / n;

    int4 co = *reinterpret_cast<const int4*>(coords + 4 * p);  // b,z,y,x
    float cx = (float)co.w * 0.16f + 0.08f;     // PX/2 + X0
    float cy = (float)co.z * 0.16f - 39.6f;     // PY/2 + Y0
    float cz = (float)co.y * 4.0f  - 1.0f;      // PZ/2 + Z0

    float w0 = sW[c],        w1 = sW[64 + c],  w2 = sW[128 + c],
          w3 = sW[192 + c],  w4 = sW[256 + c], w5 = sW[320 + c],
          w6 = sW[384 + c],  w7 = sW[448 + c], w8 = sW[512 + c],
          w9 = sW[576 + c];
    // fold: h = x*(w0+w4+w7) + y*(w1+w5+w8) + z*(w2+w6+w9) + w*w3 + off
    float Wp0 = w0 + w4 + w7, Wp1 = w1 + w5 + w8, Wp2 = w2 + w6 + w9;
    float off = -(mx * w4 + my * w5 + mz * w6 + cx * w7 + cy * w8 + cz * w9);

    float hmax = -3.4e38f, hmin = 3.4e38f, sh2 = 0.f;
    const float4* base = &sPts[lp * M_PTS];
    #pragma unroll
    for (int m = 0; m < M_PTS; m++) {
        float4 pt = base[m];                     // broadcast LDS.128
        float h = fmaf(pt.w, w3, off);
        h = fmaf(pt.x, Wp0, h);
        h = fmaf(pt.y, Wp1, h);
        h = fmaf(pt.z, Wp2, h);
        sh2  = fmaf(h, h, sh2);
        hmax = fmaxf(hmax, h);
        hmin = fminf(hmin, h);
    }

    // relu(max(h*a+b)) with a = gamma*rstd, rstd>0: need max if gamma>=0 else min
    float g   = __ldg(&gamma[c]);
    float ext = (g >= 0.f) ? hmax : hmin;
    g_ext[(size_t)p * COUTC + c] = ext;

    // Sum_m h = Sx*Wp0 + Sy*Wp1 + Sz*Wp2 + Sw*w3 + 32*off  (exact collapse)
    float sh = fmaf(S.x, Wp0, fmaf(S.y, Wp1, fmaf(S.z, Wp2,
               fmaf(S.w, w3, 32.f * off))));

    sRed[lp * COUTC + c]              = sh;
    sRed[PPB * COUTC + lp * COUTC + c] = sh2;

    if (c == 0) {  // last-occurrence-wins scatter => max pillar index wins
        int cell = co.y + co.z * NXC + co.w;    // z + y*NX + x
        atomicMax(&g_winner[co.x * NYNX + cell], p);
    }
    __syncthreads();

    if (t < 2 * COUTC) {
        int which = t >> 6;           // 0: sumh, 1: sumh2
        int cc    = t & 63;
        float acc = 0.f;
        #pragma unroll
        for (int j = 0; j < PPB; j++)
            acc += sRed[which * PPB * COUTC + j * COUTC + cc];
        if (which == 0) atomicAdd(&g_sumh[cc],  acc);
        else            atomicAdd(&g_sumh2[cc], acc);
    }
}

// ---------------- fold BN constants into per-channel (a, b) --------------
__global__ void pfe_stats(const float* __restrict__ gamma,
                          const float* __restrict__ beta)
{
    int c = threadIdx.x;
    const float invN = 1.0f / ((float)P_PILLARS * (float)M_PTS);
    float mu  = g_sumh[c] * invN;
    float var = fmaf(-mu, mu, g_sumh2[c] * invN);
    float a   = gamma[c] * rsqrtf(var + 1e-3f);
    g_a[c]  = a;
    g_bb[c] = fmaf(-mu, a, beta[c]);
}

// ---------------- output gather: full coalesced write of (B,64,NY,NX) ----
__global__ __launch_bounds__(256) void pfe_out(float* __restrict__ out)
{
    int q = blockIdx.x * 256 + threadIdx.x;
    if (q >= Q4) return;
    int bc = blockIdx.y;            // b*64 + c
    int b  = bc >> 6, c = bc & 63;

    int4 w4 = *reinterpret_cast<const int4*>(&g_winner[b * NYNX + q * 4]);
    float a = g_a[c], bb = g_bb[c];

    float4 o;
    o.x = (w4.x >= 0) ? fmaxf(fmaf(g_ext[(size_t)w4.x * COUTC + c], a, bb), 0.f) : 0.f;
    o.y = (w4.y >= 0) ? fmaxf(fmaf(g_ext[(size_t)w4.y * COUTC + c], a, bb), 0.f) : 0.f;
    o.z = (w4.z >= 0) ? fmaxf(fmaf(g_ext[(size_t)w4.z * COUTC + c], a, bb), 0.f) : 0.f;
    o.w = (w4.w >= 0) ? fmaxf(fmaf(g_ext[(size_t)w4.w * COUTC + c], a, bb), 0.f) : 0.f;

    reinterpret_cast<float4*>(out)[(size_t)bc * Q4 + q] = o;
}

// ---------------- launch ----------------
extern "C" void kernel_launch(void* const* d_in, const int* in_sizes, int n_in,
                              void* d_out, int out_size)
{
    const float* pillars    = (const float*)d_in[0];
    const int*   coords     = (const int*)  d_in[1];
    const int*   num_points = (const int*)  d_in[2];
    const float* W          = (const float*)d_in[3];
    const float* gamma      = (const float*)d_in[4];
    const float* beta       = (const float*)d_in[5];
    float* out = (float*)d_out;

    pfe_init<<<(NBC * NYNX + 255) / 256, 256>>>();
    pfe_main<<<P_PILLARS / PPB, 512>>>(pillars, coords, num_points, W, gamma);
    pfe_stats<<<1, COUTC>>>(gamma, beta);
    dim3 gd((Q4 + 255) / 256, NBC * COUTC);
    pfe_out<<<gd, 256>>>(out);
}

// round 3
// speedup vs baseline: 1.1546x; 1.1546x over previous
#include <cuda_runtime.h>

#define P_PILLARS 96000
#define M_PTS 32
#define COUTC 64
#define NXC 432
#define NYC 496
#define NBC 8
#define NYNX (NXC * NYC)        /* 214272 */
#define PPB 32                  /* pillars per block in main kernel */
#define TILE 64                 /* cells per block in output kernel */

// ---------------- device scratch (no allocations allowed) ----------------
__device__ int   g_winner[NBC * NYNX];                    // 6.9 MB
__device__ float g_sumh[COUTC];
__device__ float g_sumh2[COUTC];
__device__ float g_a[COUTC];
__device__ float g_bb[COUTC];
__device__ float g_ext[(size_t)P_PILLARS * COUTC];        // 24.6 MB

// ---------------- init: winner = -1, stats = 0 ----------------
__global__ void pfe_init() {
    int i = blockIdx.x * blockDim.x + threadIdx.x;
    if (i < NBC * NYNX) g_winner[i] = -1;
    if (i < COUTC) { g_sumh[i] = 0.f; g_sumh2[i] = 0.f; }
}

// ---------------- main: per-pillar GEMM + stats + extremes + winner ------
// 512 threads = 32 pillars x 16 threads; each thread owns 4 contiguous channels.
__global__ __launch_bounds__(512) void pfe_main(
    const float* __restrict__ pillars,
    const int*   __restrict__ coords,
    const int*   __restrict__ num_points,
    const float* __restrict__ W,
    const float* __restrict__ gamma)
{
    __shared__ float4 sPts[PPB * M_PTS];   // 16 KB
    __shared__ float  sW[640];             // 2.5 KB
    __shared__ float  sAcc[2 * COUTC];     // block stats accumulators

    int t  = threadIdx.x;
    int lp = t >> 4;          // local pillar 0..31
    int c4 = t & 15;          // channel group
    int cb = c4 * 4;          // first channel of this thread
    int p  = blockIdx.x * PPB + lp;

    // cooperative coalesced loads
    const float4* gp = reinterpret_cast<const float4*>(pillars)
                       + (size_t)blockIdx.x * PPB * M_PTS;
    sPts[t]       = gp[t];
    sPts[t + 512] = gp[t + 512];
    for (int i = t; i < 640; i += 512) sW[i] = W[i];
    if (t < 2 * COUTC) sAcc[t] = 0.f;
    __syncthreads();

    // per-pillar point sums via half-warp (16-lane) shuffle reduction
    float4 a0 = sPts[lp * M_PTS + c4];
    float4 a1 = sPts[lp * M_PTS + c4 + 16];
    float Sx = a0.x + a1.x, Sy = a0.y + a1.y, Sz = a0.z + a1.z, Sw = a0.w + a1.w;
    #pragma unroll
    for (int o = 8; o; o >>= 1) {
        Sx += __shfl_down_sync(0xffffffffu, Sx, o, 16);
        Sy += __shfl_down_sync(0xffffffffu, Sy, o, 16);
        Sz += __shfl_down_sync(0xffffffffu, Sz, o, 16);
        Sw += __shfl_down_sync(0xffffffffu, Sw, o, 16);
    }
    Sx = __shfl_sync(0xffffffffu, Sx, 0, 16);
    Sy = __shfl_sync(0xffffffffu, Sy, 0, 16);
    Sz = __shfl_sync(0xffffffffu, Sz, 0, 16);
    Sw = __shfl_sync(0xffffffffu, Sw, 0, 16);

    float n  = (float)__ldg(&num_points[p]);
    float mx = Sx / n, my = Sy / n, mz = Sz / n;

    int4 co = *reinterpret_cast<const int4*>(coords + 4 * p);  // b,z,y,x
    float cx = (float)co.w * 0.16f + 0.08f;     // PX/2 + X0
    float cy = (float)co.z * 0.16f - 39.6f;     // PY/2 + Y0
    float cz = (float)co.y * 4.0f  - 1.0f;      // PZ/2 + Z0

    // weights for 4 channels: rows 0..9, float4 each
    const float4* W4 = reinterpret_cast<const float4*>(sW);
    float Wr[10][4];
    #pragma unroll
    for (int i = 0; i < 10; i++) {
        float4 r = W4[i * 16 + c4];
        Wr[i][0] = r.x; Wr[i][1] = r.y; Wr[i][2] = r.z; Wr[i][3] = r.w;
    }

    float Wp0[4], Wp1[4], Wp2[4], off[4];
    #pragma unroll
    for (int k = 0; k < 4; k++) {
        Wp0[k] = Wr[0][k] + Wr[4][k] + Wr[7][k];
        Wp1[k] = Wr[1][k] + Wr[5][k] + Wr[8][k];
        Wp2[k] = Wr[2][k] + Wr[6][k] + Wr[9][k];
        off[k] = -(mx * Wr[4][k] + my * Wr[5][k] + mz * Wr[6][k]
                 + cx * Wr[7][k] + cy * Wr[8][k] + cz * Wr[9][k]);
    }

    float hmax[4], hmin[4], sh2[4];
    #pragma unroll
    for (int k = 0; k < 4; k++) { hmax[k] = -3.4e38f; hmin[k] = 3.4e38f; sh2[k] = 0.f; }

    const float4* base = &sPts[lp * M_PTS];
    #pragma unroll
    for (int m = 0; m < M_PTS; m++) {
        float4 pt = base[m];                     // broadcast LDS.128
        #pragma unroll
        for (int k = 0; k < 4; k++) {
            float h = fmaf(pt.w, Wr[3][k], off[k]);
            h = fmaf(pt.x, Wp0[k], h);
            h = fmaf(pt.y, Wp1[k], h);
            h = fmaf(pt.z, Wp2[k], h);
            sh2[k]  = fmaf(h, h, sh2[k]);
            hmax[k] = fmaxf(hmax[k], h);
            hmin[k] = fminf(hmin[k], h);
        }
    }

    // relu(max(h*a+b)) with a = gamma*rstd, rstd>0: need max if gamma>=0 else min
    float4 gv = *reinterpret_cast<const float4*>(&gamma[cb]);
    float4 e;
    e.x = (gv.x >= 0.f) ? hmax[0] : hmin[0];
    e.y = (gv.y >= 0.f) ? hmax[1] : hmin[1];
    e.z = (gv.z >= 0.f) ? hmax[2] : hmin[2];
    e.w = (gv.w >= 0.f) ? hmax[3] : hmin[3];
    *reinterpret_cast<float4*>(&g_ext[(size_t)p * COUTC + cb]) = e;

    // Sum_m h collapses exactly to pillar point-sums
    #pragma unroll
    for (int k = 0; k < 4; k++) {
        float sh = fmaf(Sx, Wp0[k], fmaf(Sy, Wp1[k], fmaf(Sz, Wp2[k],
                   fmaf(Sw, Wr[3][k], 32.f * off[k]))));
        atomicAdd(&sAcc[cb + k], sh);
        atomicAdd(&sAcc[COUTC + cb + k], sh2[k]);
    }

    if (c4 == 0) {  // last-occurrence-wins scatter => max pillar index wins
        int cell = co.y + co.z * NXC + co.w;    // z + y*NX + x
        atomicMax(&g_winner[co.x * NYNX + cell], p);
    }
    __syncthreads();

    if (t < COUTC)            atomicAdd(&g_sumh[t],          sAcc[t]);
    else if (t < 2 * COUTC)   atomicAdd(&g_sumh2[t - COUTC], sAcc[t]);
}

// ---------------- fold BN constants into per-channel (a, b) --------------
__global__ void pfe_stats(const float* __restrict__ gamma,
                          const float* __restrict__ beta)
{
    int c = threadIdx.x;
    const float invN = 1.0f / ((float)P_PILLARS * (float)M_PTS);
    float mu  = g_sumh[c] * invN;
    float var = fmaf(-mu, mu, g_sumh2[c] * invN);
    float a   = gamma[c] * rsqrtf(var + 1e-3f);
    g_a[c]  = a;
    g_bb[c] = fmaf(-mu, a, beta[c]);
}

// ---------------- output: tiled gather + smem transpose, coalesced -------
// block = 64 cells x 64 channels for one batch; winners read ONCE, ext
// gathers coalesced (threads span channels of one winner).
__global__ __launch_bounds__(256) void pfe_out(float* __restrict__ out)
{
    __shared__ int   sWin[TILE];
    __shared__ float sTile[TILE * 65];   // pad 65 -> conflict-free transpose

    int b     = blockIdx.y;
    int cell0 = blockIdx.x * TILE;
    int t     = threadIdx.x;

    if (t < TILE) sWin[t] = g_winner[b * NYNX + cell0 + t];
    __syncthreads();

    int c  = t & 63;
    int jj = t >> 6;
    float a = g_a[c], bb = g_bb[c];
    #pragma unroll
    for (int i = jj; i < TILE; i += 4) {
        int w = sWin[i];
        float v = 0.f;
        if (w >= 0)
            v = fmaxf(fmaf(g_ext[(size_t)w * COUTC + c], a, bb), 0.f);
        sTile[i * 65 + c] = v;
    }
    __syncthreads();

    // write phase: float4 across cells, contiguous per channel row
    int col4 = t & 15;        // cell group of 4
    int cr   = t >> 4;        // 0..15
    size_t outBase = (size_t)(b * COUTC) * NYNX + cell0;
    #pragma unroll
    for (int cc = cr; cc < COUTC; cc += 16) {
        float4 v;
        v.x = sTile[(col4 * 4 + 0) * 65 + cc];
        v.y = sTile[(col4 * 4 + 1) * 65 + cc];
        v.z = sTile[(col4 * 4 + 2) * 65 + cc];
        v.w = sTile[(col4 * 4 + 3) * 65 + cc];
        *reinterpret_cast<float4*>(&out[outBase + (size_t)cc * NYNX + col4 * 4]) = v;
    }
}

// ---------------- launch ----------------
extern "C" void kernel_launch(void* const* d_in, const int* in_sizes, int n_in,
                              void* d_out, int out_size)
{
    const float* pillars    = (const float*)d_in[0];
    const int*   coords     = (const int*)  d_in[1];
    const int*   num_points = (const int*)  d_in[2];
    const float* W          = (const float*)d_in[3];
    const float* gamma      = (const float*)d_in[4];
    const float* beta       = (const float*)d_in[5];
    float* out = (float*)d_out;

    pfe_init<<<(NBC * NYNX + 255) / 256, 256>>>();
    pfe_main<<<P_PILLARS / PPB, 512>>>(pillars, coords, num_points, W, gamma);
    pfe_stats<<<1, COUTC>>>(gamma, beta);
    dim3 gd(NYNX / TILE, NBC);
    pfe_out<<<gd, 256>>>(out);
}